// round 4
// baseline (speedup 1.0000x reference)
#include <cuda_runtime.h>
#include <cstddef>

// Grefenstette stack forward, closed-form reformulation.
//
//   s_t[j] = relu(d_j - relu(M_{j,t} - H_j)),  M_{j,t} = max_{j<tau<=t} G_tau
//     G_tau = P_tau - D_{tau-1},  H_j = P_j - D_j,  P = cumsum(u), D = cumsum(d)
//   w_t[j] = min(1, R_t[j]) - min(1, R_t[j+1]),  R = suffix-sum of s_t
//   out[t,b,:] = sum_j w_t[j] * v[j,b,:]
//
// Kernel 1 (block per batch): fp64 shuffle-scan prefix sums, then 16 warps
// compute compact (w, j) pair lists for all 512 t's via warp-scan chunks
// over smem. Kernel 2: pure sparse gather, one warp per (t,b).

#define TT 512
#define BB 128
#define EE 256

#define K 16
#define OVER_FLAG 0x10000
#define WARPS 8
#define FULL 0xFFFFFFFFu

__device__ float  g_G[BB][TT];
__device__ float  g_H[BB][TT];
__device__ float  g_D[BB][TT];
__device__ float2 g_pairs[(size_t)TT * BB * K];   // (w, bitcast j)
__device__ int    g_cnt[TT * BB];                 // count | OVER_FLAG
__device__ float4 g_resume[TT * BB];              // (carryM, carryAcc, bitcast jtop, -)

// ---------------------------------------------------------------------------
// Kernel 1: prefix sums + pair-list construction. One block per batch.
// ---------------------------------------------------------------------------
__global__ __launch_bounds__(TT) void scan_pairs_kernel(
    const float* __restrict__ u, const float* __restrict__ d) {
    __shared__ double wsU[16];
    __shared__ double wsD[16];
    __shared__ float  sG[TT];
    __shared__ float  sH[TT];
    __shared__ float  sD[TT];

    const int b    = blockIdx.x;
    const int t    = threadIdx.x;
    const int wid  = t >> 5;
    const int lane = t & 31;

    const float uv = u[t * BB + b];
    const float dv = d[t * BB + b];

    // fp64 inclusive scan: shuffle within warp, smem across warps.
    double xu = (double)uv;
    double xd = (double)dv;
    #pragma unroll
    for (int o = 1; o < 32; o <<= 1) {
        const double yu = __shfl_up_sync(FULL, xu, o);
        const double yd = __shfl_up_sync(FULL, xd, o);
        if (lane >= o) { xu += yu; xd += yd; }
    }
    if (lane == 31) { wsU[wid] = xu; wsD[wid] = xd; }
    __syncthreads();
    if (wid == 0) {
        double tu = (lane < 16) ? wsU[lane] : 0.0;
        double td = (lane < 16) ? wsD[lane] : 0.0;
        #pragma unroll
        for (int o = 1; o < 16; o <<= 1) {
            const double yu = __shfl_up_sync(FULL, tu, o);
            const double yd = __shfl_up_sync(FULL, td, o);
            if (lane >= o) { tu += yu; td += yd; }
        }
        if (lane < 16) { wsU[lane] = tu; wsD[lane] = td; }
    }
    __syncthreads();
    const double offU = (wid > 0) ? wsU[wid - 1] : 0.0;
    const double offD = (wid > 0) ? wsD[wid - 1] : 0.0;

    const double P  = xu + offU;
    const double Dc = xd + offD;

    const float G = (float)(P - (Dc - (double)dv));  // P_t - D_{t-1}
    const float H = (float)(P - Dc);                 // P_t - D_t
    sG[t] = G;  sH[t] = H;  sD[t] = dv;
    g_G[b][t] = G;  g_H[b][t] = H;  g_D[b][t] = dv;  // for overflow resume
    __syncthreads();

    // Pair lists: warp `wid` handles t = wid*32 .. wid*32+31.
    for (int i = 0; i < 32; ++i) {
        const int tt = wid * 32 + i;

        float carryM   = -1e30f;
        float carryAcc = 0.f;
        int   cnt      = 0;
        bool  over     = false;
        float2* pp = &g_pairs[((size_t)tt * BB + b) * K];

        for (int jtop = tt; jtop >= 0 && carryAcc < 1.f; jtop -= 32) {
            const int  j  = jtop - lane;
            const bool ok = (j >= 0);

            float m = ok ? sG[j] : -1e30f;
            const float Hj = ok ? sH[j] : 0.f;
            const float Dj = ok ? sD[j] : 0.f;

            // Inclusive forward max-scan of G over lanes.
            #pragma unroll
            for (int o = 1; o < 32; o <<= 1) {
                const float x = __shfl_up_sync(FULL, m, o);
                if (lane >= o) m = fmaxf(m, x);
            }
            float Me = __shfl_up_sync(FULL, m, 1);
            if (lane == 0) Me = -1e30f;
            Me = fmaxf(Me, carryM);

            const float s = ok ? fmaxf(Dj - fmaxf(Me - Hj, 0.f), 0.f) : 0.f;

            // Inclusive forward sum-scan of s over lanes.
            float a = s;
            #pragma unroll
            for (int o = 1; o < 32; o <<= 1) {
                const float x = __shfl_up_sync(FULL, a, o);
                if (lane >= o) a += x;
            }
            const float accInc = carryAcc + a;
            const float accExc = accInc - s;
            const float w = fminf(accInc, 1.f) - fminf(accExc, 1.f);

            const unsigned mask = __ballot_sync(FULL, w > 0.f);
            const int npair = __popc(mask);
            if (cnt + npair > K) {  // rare: record resume state, bail to gather
                over = true;
                if (lane == 0)
                    g_resume[tt * BB + b] =
                        make_float4(carryM, carryAcc, __int_as_float(jtop), 0.f);
                break;
            }
            if (w > 0.f) {
                const int pos = cnt + __popc(mask & ((1u << lane) - 1u));
                pp[pos] = make_float2(w, __int_as_float(jtop - lane));
            }
            cnt += npair;

            carryAcc = __shfl_sync(FULL, accInc, 31);
            carryM   = fmaxf(carryM, __shfl_sync(FULL, m, 31));
        }

        if (lane == 0) g_cnt[tt * BB + b] = cnt | (over ? OVER_FLAG : 0);
    }
}

// ---------------------------------------------------------------------------
// Kernel 2: sparse gather. One warp per (t, b); lanes cover E with float4.
// ---------------------------------------------------------------------------
__global__ __launch_bounds__(WARPS * 32) void gather_kernel(
    const float* __restrict__ v, float* __restrict__ out) {
    const int tid  = threadIdx.x;
    const int warp = tid >> 5;
    const int lane = tid & 31;
    const int t    = blockIdx.x * WARPS + warp;
    const int b    = blockIdx.y;
    const int idx  = t * BB + b;

    const float4* __restrict__ v4 = reinterpret_cast<const float4*>(v);
    float4* __restrict__ o4       = reinterpret_cast<float4*>(out);

    float4 r0 = make_float4(0.f, 0.f, 0.f, 0.f);
    float4 r1 = make_float4(0.f, 0.f, 0.f, 0.f);

    const int craw = g_cnt[idx];
    const int cnt  = craw & 0xFFFF;
    const float2* __restrict__ pp = &g_pairs[(size_t)idx * K];

    for (int k = 0; k < cnt; ++k) {
        const float2 p = pp[k];                // broadcast load
        const float  w = p.x;
        const int    j = __float_as_int(p.y);
        const float4* vp = v4 + ((size_t)j * BB + b) * (EE / 4);
        const float4 a0 = __ldg(vp + lane);
        const float4 a1 = __ldg(vp + lane + 32);
        r0.x = fmaf(w, a0.x, r0.x);
        r0.y = fmaf(w, a0.y, r0.y);
        r0.z = fmaf(w, a0.z, r0.z);
        r0.w = fmaf(w, a0.w, r0.w);
        r1.x = fmaf(w, a1.x, r1.x);
        r1.y = fmaf(w, a1.y, r1.y);
        r1.z = fmaf(w, a1.z, r1.z);
        r1.w = fmaf(w, a1.w, r1.w);
    }

    if (craw & OVER_FLAG) {  // rare exact continuation, warp-scan chunks
        const float4 rs = g_resume[idx];
        float carryM   = rs.x;
        float carryAcc = rs.y;
        for (int jtop = __float_as_int(rs.z); jtop >= 0 && carryAcc < 1.f;
             jtop -= 32) {
            const int  j  = jtop - lane;
            const bool ok = (j >= 0);

            float m = ok ? g_G[b][j] : -1e30f;
            const float Hj = ok ? g_H[b][j] : 0.f;
            const float Dj = ok ? g_D[b][j] : 0.f;

            #pragma unroll
            for (int o = 1; o < 32; o <<= 1) {
                const float x = __shfl_up_sync(FULL, m, o);
                if (lane >= o) m = fmaxf(m, x);
            }
            float Me = __shfl_up_sync(FULL, m, 1);
            if (lane == 0) Me = -1e30f;
            Me = fmaxf(Me, carryM);

            const float s = ok ? fmaxf(Dj - fmaxf(Me - Hj, 0.f), 0.f) : 0.f;

            float a = s;
            #pragma unroll
            for (int o = 1; o < 32; o <<= 1) {
                const float x = __shfl_up_sync(FULL, a, o);
                if (lane >= o) a += x;
            }
            const float accInc = carryAcc + a;
            const float accExc = accInc - s;
            const float w = fminf(accInc, 1.f) - fminf(accExc, 1.f);

            unsigned mask = __ballot_sync(FULL, w > 0.f);
            while (mask) {
                const int src = __ffs(mask) - 1;
                mask &= mask - 1;
                const float wj = __shfl_sync(FULL, w, src);
                const int   jj = jtop - src;
                const float4* vp = v4 + ((size_t)jj * BB + b) * (EE / 4);
                const float4 a0 = __ldg(vp + lane);
                const float4 a1 = __ldg(vp + lane + 32);
                r0.x = fmaf(wj, a0.x, r0.x);
                r0.y = fmaf(wj, a0.y, r0.y);
                r0.z = fmaf(wj, a0.z, r0.z);
                r0.w = fmaf(wj, a0.w, r0.w);
                r1.x = fmaf(wj, a1.x, r1.x);
                r1.y = fmaf(wj, a1.y, r1.y);
                r1.z = fmaf(wj, a1.z, r1.z);
                r1.w = fmaf(wj, a1.w, r1.w);
            }

            carryAcc = __shfl_sync(FULL, accInc, 31);
            carryM   = fmaxf(carryM, __shfl_sync(FULL, m, 31));
        }
    }

    float4* op = o4 + ((size_t)t * BB + b) * (EE / 4);
    op[lane]      = r0;
    op[lane + 32] = r1;
}

extern "C" void kernel_launch(void* const* d_in, const int* in_sizes, int n_in,
                              void* d_out, int out_size) {
    const float* v = (const float*)d_in[0];  // [T,B,E]
    const float* u = (const float*)d_in[1];  // [T,B]
    const float* d = (const float*)d_in[2];  // [T,B]
    float* out     = (float*)d_out;          // [T,B,E]

    scan_pairs_kernel<<<BB, TT>>>(u, d);

    dim3 grid(TT / WARPS, BB);
    gather_kernel<<<grid, WARPS * 32>>>(v, out);
}

// round 5
// speedup vs baseline: 2.5282x; 2.5282x over previous
#include <cuda_runtime.h>
#include <cstddef>

// Grefenstette stack forward, closed-form reformulation.
//
//   s_t[j] = relu(d_j - relu(M_{j,t} - H_j)),  M_{j,t} = max_{j<tau<=t} G_tau
//     G_tau = P_tau - D_{tau-1},  H_j = P_j - D_j,  P = cumsum(u), D = cumsum(d)
//   w_t[j] = min(1, R_t[j]) - min(1, R_t[j+1]),  R = suffix-sum of s_t
//   out[t,b,:] = sum_j w_t[j] * v[j,b,:]
//
// K1: fp64 shuffle-scan prefix sums -> G,H,D [B][T].
// K2: warp per (t,b) at high occupancy: warp-scan chunks -> compact (w,j) lists.
// K3: sparse gather, warp per 4 consecutive t's (row reuse in L1/L2).

#define TT 512
#define BB 128
#define EE 256

#define K 16
#define OVER_FLAG 0x10000
#define FULL 0xFFFFFFFFu

#define PW 8     // pairs_kernel warps per block
#define GW 8     // gather warps per block
#define TPW 4    // t's per gather warp

__device__ float  g_G[BB][TT];
__device__ float  g_H[BB][TT];
__device__ float  g_D[BB][TT];
__device__ float2 g_pairs[(size_t)TT * BB * K];   // (w, bitcast j)
__device__ int    g_cnt[TT * BB];                 // count | OVER_FLAG
__device__ float4 g_resume[TT * BB];              // (carryM, carryAcc, bitcast jtop, -)

// ---------------------------------------------------------------------------
// Kernel 1: fp64 prefix sums (shuffle scan, 2 syncs). One block per batch.
// ---------------------------------------------------------------------------
__global__ __launch_bounds__(TT) void scan_kernel(const float* __restrict__ u,
                                                  const float* __restrict__ d) {
    __shared__ double wsU[16];
    __shared__ double wsD[16];

    const int b    = blockIdx.x;
    const int t    = threadIdx.x;
    const int wid  = t >> 5;
    const int lane = t & 31;

    const float uv = u[t * BB + b];
    const float dv = d[t * BB + b];

    double xu = (double)uv;
    double xd = (double)dv;
    #pragma unroll
    for (int o = 1; o < 32; o <<= 1) {
        const double yu = __shfl_up_sync(FULL, xu, o);
        const double yd = __shfl_up_sync(FULL, xd, o);
        if (lane >= o) { xu += yu; xd += yd; }
    }
    if (lane == 31) { wsU[wid] = xu; wsD[wid] = xd; }
    __syncthreads();
    if (wid == 0) {
        double tu = (lane < 16) ? wsU[lane] : 0.0;
        double td = (lane < 16) ? wsD[lane] : 0.0;
        #pragma unroll
        for (int o = 1; o < 16; o <<= 1) {
            const double yu = __shfl_up_sync(FULL, tu, o);
            const double yd = __shfl_up_sync(FULL, td, o);
            if (lane >= o) { tu += yu; td += yd; }
        }
        if (lane < 16) { wsU[lane] = tu; wsD[lane] = td; }
    }
    __syncthreads();
    const double offU = (wid > 0) ? wsU[wid - 1] : 0.0;
    const double offD = (wid > 0) ? wsD[wid - 1] : 0.0;

    const double P  = xu + offU;
    const double Dc = xd + offD;

    g_G[b][t] = (float)(P - (Dc - (double)dv));  // P_t - D_{t-1}
    g_H[b][t] = (float)(P - Dc);                 // P_t - D_t
    g_D[b][t] = dv;
}

// ---------------------------------------------------------------------------
// Kernel 2: pair lists. One warp per (t,b), grid (TT/PW, BB).
// ---------------------------------------------------------------------------
__global__ __launch_bounds__(PW * 32) void pairs_kernel() {
    const int tid  = threadIdx.x;
    const int warp = tid >> 5;
    const int lane = tid & 31;
    const int t    = blockIdx.x * PW + warp;
    const int b    = blockIdx.y;

    float carryM   = -1e30f;
    float carryAcc = 0.f;
    int   cnt      = 0;
    bool  over     = false;
    float2* pp = &g_pairs[((size_t)t * BB + b) * K];

    for (int jtop = t; jtop >= 0 && carryAcc < 1.f; jtop -= 32) {
        const int  j  = jtop - lane;
        const bool ok = (j >= 0);

        float m        = ok ? g_G[b][j] : -1e30f;
        const float Hj = ok ? g_H[b][j] : 0.f;
        const float Dj = ok ? g_D[b][j] : 0.f;

        // Inclusive forward max-scan of G over lanes (lane 0 = top slot).
        #pragma unroll
        for (int o = 1; o < 32; o <<= 1) {
            const float x = __shfl_up_sync(FULL, m, o);
            if (lane >= o) m = fmaxf(m, x);
        }
        float Me = __shfl_up_sync(FULL, m, 1);
        if (lane == 0) Me = -1e30f;
        Me = fmaxf(Me, carryM);

        const float s = ok ? fmaxf(Dj - fmaxf(Me - Hj, 0.f), 0.f) : 0.f;

        // Inclusive forward sum-scan of s over lanes.
        float a = s;
        #pragma unroll
        for (int o = 1; o < 32; o <<= 1) {
            const float x = __shfl_up_sync(FULL, a, o);
            if (lane >= o) a += x;
        }
        const float accInc = carryAcc + a;
        const float accExc = accInc - s;
        const float w = fminf(accInc, 1.f) - fminf(accExc, 1.f);

        const unsigned mask = __ballot_sync(FULL, w > 0.f);
        const int npair = __popc(mask);
        if (cnt + npair > K) {  // rare: resume in gather
            over = true;
            if (lane == 0)
                g_resume[t * BB + b] =
                    make_float4(carryM, carryAcc, __int_as_float(jtop), 0.f);
            break;
        }
        if (w > 0.f) {
            const int pos = cnt + __popc(mask & ((1u << lane) - 1u));
            pp[pos] = make_float2(w, __int_as_float(jtop - lane));
        }
        cnt += npair;

        carryAcc = __shfl_sync(FULL, accInc, 31);
        carryM   = fmaxf(carryM, __shfl_sync(FULL, m, 31));
    }

    if (lane == 0) g_cnt[t * BB + b] = cnt | (over ? OVER_FLAG : 0);
}

// ---------------------------------------------------------------------------
// Kernel 3: sparse gather. One warp per TPW consecutive t's of one batch.
// ---------------------------------------------------------------------------
__global__ __launch_bounds__(GW * 32) void gather_kernel(
    const float* __restrict__ v, float* __restrict__ out) {
    const int tid   = threadIdx.x;
    const int warp  = tid >> 5;
    const int lane  = tid & 31;
    const int tbase = (blockIdx.x * GW + warp) * TPW;
    const int b     = blockIdx.y;

    const float4* __restrict__ v4 = reinterpret_cast<const float4*>(v);
    float4* __restrict__ o4       = reinterpret_cast<float4*>(out);

    #pragma unroll
    for (int i = 0; i < TPW; ++i) {
        const int t   = tbase + i;
        const int idx = t * BB + b;

        float4 r0 = make_float4(0.f, 0.f, 0.f, 0.f);
        float4 r1 = make_float4(0.f, 0.f, 0.f, 0.f);

        const int craw = g_cnt[idx];
        const int cnt  = craw & 0xFFFF;
        const float2* __restrict__ pp = &g_pairs[(size_t)idx * K];

        for (int k = 0; k < cnt; ++k) {
            const float2 p = pp[k];            // broadcast load
            const float  w = p.x;
            const int    j = __float_as_int(p.y);
            const float4* vp = v4 + ((size_t)j * BB + b) * (EE / 4);
            const float4 a0 = __ldg(vp + lane);
            const float4 a1 = __ldg(vp + lane + 32);
            r0.x = fmaf(w, a0.x, r0.x);
            r0.y = fmaf(w, a0.y, r0.y);
            r0.z = fmaf(w, a0.z, r0.z);
            r0.w = fmaf(w, a0.w, r0.w);
            r1.x = fmaf(w, a1.x, r1.x);
            r1.y = fmaf(w, a1.y, r1.y);
            r1.z = fmaf(w, a1.z, r1.z);
            r1.w = fmaf(w, a1.w, r1.w);
        }

        if (craw & OVER_FLAG) {  // rare exact continuation
            const float4 rs = g_resume[idx];
            float carryM   = rs.x;
            float carryAcc = rs.y;
            for (int jtop = __float_as_int(rs.z); jtop >= 0 && carryAcc < 1.f;
                 jtop -= 32) {
                const int  j  = jtop - lane;
                const bool ok = (j >= 0);

                float m        = ok ? g_G[b][j] : -1e30f;
                const float Hj = ok ? g_H[b][j] : 0.f;
                const float Dj = ok ? g_D[b][j] : 0.f;

                #pragma unroll
                for (int o = 1; o < 32; o <<= 1) {
                    const float x = __shfl_up_sync(FULL, m, o);
                    if (lane >= o) m = fmaxf(m, x);
                }
                float Me = __shfl_up_sync(FULL, m, 1);
                if (lane == 0) Me = -1e30f;
                Me = fmaxf(Me, carryM);

                const float s = ok ? fmaxf(Dj - fmaxf(Me - Hj, 0.f), 0.f) : 0.f;

                float a = s;
                #pragma unroll
                for (int o = 1; o < 32; o <<= 1) {
                    const float x = __shfl_up_sync(FULL, a, o);
                    if (lane >= o) a += x;
                }
                const float accInc = carryAcc + a;
                const float accExc = accInc - s;
                const float w = fminf(accInc, 1.f) - fminf(accExc, 1.f);

                unsigned mask = __ballot_sync(FULL, w > 0.f);
                while (mask) {
                    const int src = __ffs(mask) - 1;
                    mask &= mask - 1;
                    const float wj = __shfl_sync(FULL, w, src);
                    const int   jj = jtop - src;
                    const float4* vp = v4 + ((size_t)jj * BB + b) * (EE / 4);
                    const float4 a0 = __ldg(vp + lane);
                    const float4 a1 = __ldg(vp + lane + 32);
                    r0.x = fmaf(wj, a0.x, r0.x);
                    r0.y = fmaf(wj, a0.y, r0.y);
                    r0.z = fmaf(wj, a0.z, r0.z);
                    r0.w = fmaf(wj, a0.w, r0.w);
                    r1.x = fmaf(wj, a1.x, r1.x);
                    r1.y = fmaf(wj, a1.y, r1.y);
                    r1.z = fmaf(wj, a1.z, r1.z);
                    r1.w = fmaf(wj, a1.w, r1.w);
                }

                carryAcc = __shfl_sync(FULL, accInc, 31);
                carryM   = fmaxf(carryM, __shfl_sync(FULL, m, 31));
            }
        }

        float4* op = o4 + ((size_t)idx) * (EE / 4);
        op[lane]      = r0;
        op[lane + 32] = r1;
    }
}

extern "C" void kernel_launch(void* const* d_in, const int* in_sizes, int n_in,
                              void* d_out, int out_size) {
    const float* v = (const float*)d_in[0];  // [T,B,E]
    const float* u = (const float*)d_in[1];  // [T,B]
    const float* d = (const float*)d_in[2];  // [T,B]
    float* out     = (float*)d_out;          // [T,B,E]

    scan_kernel<<<BB, TT>>>(u, d);

    dim3 pgrid(TT / PW, BB);
    pairs_kernel<<<pgrid, PW * 32>>>();

    dim3 ggrid(TT / (GW * TPW), BB);
    gather_kernel<<<ggrid, GW * 32>>>(v, out);
}